// round 11
// baseline (speedup 1.0000x reference)
#include <cuda_runtime.h>
#include <math.h>
#include <stdint.h>

// Problem constants (fixed by the dataset shapes)
#define Bq    8
#define Aq    64
#define DE    128
#define DH    64
#define Mq    512            // N*L = 8*64
#define ZDIM  128
#define ZE    64
#define ZH    64
#define SPLIT 4              // m-splits per (b,a)
#define MBLK  (Mq / SPLIT)   // 128 m per block
#define MPW   (MBLK / 4)     // 32 m per warp
#define NCHUNK 8             // 4 m per chunk
#define MAXN  0.99999f       // (1 - 1e-5)/sqrt(c), c = 1
#define ARGC  0.9999999f     // 1 - 1e-7

// Scratch (device globals: no allocation in kernel_launch)
__device__ float g_dH2[Bq * Mq];                       // 16 KB
__device__ float g_logv[Bq * Mq * DH];                 // 1 MB (L2-resident)
__device__ float g_pmx[Bq * Aq * SPLIT];               // partial max
__device__ float g_psm[Bq * Aq * SPLIT];               // partial sum-exp
__device__ float g_pe [Bq * Aq * SPLIT * DE];          // partial e-acc
__device__ float g_pv [Bq * Aq * SPLIT * DH];          // partial v-acc

__device__ __forceinline__ float wredsum(float v) {
#pragma unroll
    for (int o = 16; o; o >>= 1) v += __shfl_xor_sync(0xffffffffu, v, o);
    return v;
}

__device__ __forceinline__ uint32_t smem_u32(const void* p) {
    return (uint32_t)__cvta_generic_to_shared(p);
}
__device__ __forceinline__ void cp_async16(uint32_t dst, const void* src) {
    asm volatile("cp.async.cg.shared.global [%0], [%1], 16;\n" :: "r"(dst), "l"(src));
}
__device__ __forceinline__ void cp_commit() {
    asm volatile("cp.async.commit_group;\n" ::: "memory");
}
template <int N>
__device__ __forceinline__ void cp_wait() {
    asm volatile("cp.async.wait_group %0;\n" :: "n"(N) : "memory");
}

// ---------------------------------------------------------------------------
// Kernel 1: per (b, m) hyperbolic precompute (unchanged from R8, passing).
// ---------------------------------------------------------------------------
__global__ __launch_bounds__(128) void k_hyp(
    const float* __restrict__ curr_hyp,   // [B, DH]
    const float* __restrict__ demo_hyp)   // [B, M, DH]
{
    int warp = threadIdx.x >> 5, lane = threadIdx.x & 31;
    int idx  = blockIdx.x * 4 + warp;     // [0, B*M)
    int b    = idx >> 9;                  // Mq = 512

    const float2 xv = ((const float2*)(curr_hyp + (size_t)b * DH))[lane];
    const float2 yv = ((const float2*)(demo_hyp + (size_t)idx * DH))[lane];

    float pxn = fmaf(xv.x, xv.x, xv.y * xv.y);
    float pyn = fmaf(yv.x, yv.x, yv.y * yv.y);
    float pxy = fmaf(xv.x, yv.x, xv.y * yv.y);
#pragma unroll
    for (int o = 16; o; o >>= 1) {        // 3 independent chains, interleaved
        pxn += __shfl_xor_sync(0xffffffffu, pxn, o);
        pyn += __shfl_xor_sync(0xffffffffu, pyn, o);
        pxy += __shfl_xor_sync(0xffffffffu, pxy, o);
    }

    float xnorm = fmaxf(sqrtf(pxn), 1e-15f);
    float sx    = xnorm > MAXN ? __fdividef(MAXN, xnorm) : 1.0f;
    float ynorm = fmaxf(sqrtf(pyn), 1e-15f);
    float sy    = ynorm > MAXN ? __fdividef(MAXN, ynorm) : 1.0f;

    float x2 = pxn * sx * sx, y2 = pyn * sy * sy, xy = pxy * sx * sy;

    float cA  = 1.0f - 2.0f * xy + y2;    // coeff of a = -x
    float cY  = 1.0f - x2;                // coeff of y
    float den = 1.0f - 2.0f * xy + x2 * y2;
    float id  = __fdividef(1.0f, fmaxf(den, 1e-15f));

    // |u|^2 = id^2 * (cA^2 x2 - 2 cA cY xy + cY^2 y2)
    float un2   = (cA * cA * x2 - 2.0f * cA * cY * xy + cY * cY * y2) * id * id;
    float unorm = fmaxf(sqrtf(un2), 1e-15f);
    float arg   = fminf(unorm, ARGC);
    float at    = 0.5f * __logf(__fdividef(1.0f + arg, 1.0f - arg));   // atanh

    float scale = fmaxf(cY, 1e-15f) * __fdividef(at, unorm);

    float u0 = (cA * (-(xv.x * sx)) + cY * (yv.x * sy)) * id;
    float u1 = (cA * (-(xv.y * sx)) + cY * (yv.y * sy)) * id;

    ((float2*)(g_logv + (size_t)idx * DH))[lane] = make_float2(scale * u0, scale * u1);
    if (lane == 0) { float d = 2.0f * at; g_dH2[idx] = d * d; }
}

// ---------------------------------------------------------------------------
// Kernel 2: partial online-softmax attention, SEGMENTED-LANE layout.
// Warp = 4 segments x 8 lanes. Chunk = 4 m (one per segment). Lane (seg,sub)
// owns dims 16*sub..16*sub+15 of segment seg's m. Per chunk: 5 SHFL total
// (3 segment-reduce + 2 warp-max) and 1 expf per lane, vs 20 SHFL + 4 expf
// in the per-m layout. m-rows stored TRANSPOSED in smem so the strided
// 8-lane reads are bank-conflict-free:
//   rho row (32 float4): logical f -> physical (f&3)*8 + (f>>2)
//   lv  row (16 float4): logical f -> physical (f&1)*8 + (f>>1)
// Read back: lane k-th float4 at physical k*8 + sub (8 lanes tile one 128B
// window per LDS.128 phase -> conflict-free).
// ---------------------------------------------------------------------------
__global__ __launch_bounds__(128) void k_attn_part(
    const float* __restrict__ curr_rho,   // [B, A, DE]
    const float* __restrict__ demo_rho)   // [B, M, A, DE]
{
    int bas = blockIdx.x;                 // ((b*64 + a)*SPLIT + s)
    int s   = bas & (SPLIT - 1);
    int ba  = bas >> 2;
    int b   = ba >> 6, a = ba & 63;
    int tid = threadIdx.x, warp = tid >> 5, lane = tid & 31;
    int seg = lane >> 3, sub = lane & 7;

    __shared__ float4 sm_rho[8][4][32];   // 16 KB: 8 m-slots, transposed rows
    __shared__ float4 sm_lv [8][4][16];   //  8 KB
    __shared__ float  s_dH2[MBLK];        // 512 B
    __shared__ float  s_mx[4], s_sm[4];
    __shared__ float4 s_e4[4][32];        // 2 KB merge
    __shared__ float4 s_v4[4][16];        // 1 KB merge

    const float* rho_b = demo_rho + ((size_t)b * Mq * Aq + a) * DE + 4 * lane;
    const float* lv_b  = g_logv + (size_t)b * Mq * DH;
    int m0 = s * MBLK + warp;             // this warp's first m; stride 4

    // prologue: 2 chunks, issued before the staging barrier
#pragma unroll
    for (int c = 0; c < 2; ++c) {
#pragma unroll
        for (int j = 0; j < 4; ++j) {     // rho row j: lane copies float4 'lane'
            int m = m0 + 16 * c + 4 * j;
            cp_async16(smem_u32(&sm_rho[4 * c + j][warp][(lane & 3) * 8 + (lane >> 2)]),
                       rho_b + (size_t)m * Aq * DE);
        }
#pragma unroll
        for (int t = 0; t < 2; ++t) {     // lv rows: 64 float4s over 32 lanes x2
            int item = t * 32 + lane;
            int j = item >> 4, f = item & 15;
            int m = m0 + 16 * c + 4 * j;
            cp_async16(smem_u32(&sm_lv[4 * c + j][warp][(f & 1) * 8 + (f >> 1)]),
                       lv_b + (size_t)m * DH + 4 * f);
        }
        cp_commit();
    }

    s_dH2[tid] = g_dH2[(size_t)b * Mq + s * MBLK + tid];
    __syncthreads();

    // query slice: 16 dims per lane (same for all segments)
    float4 cr4[4];
#pragma unroll
    for (int k = 0; k < 4; ++k)
        cr4[k] = ((const float4*)(curr_rho + ((size_t)b * Aq + a) * DE))[4 * sub + k];

    float  mx = -INFINITY, sm = 0.0f;
    float4 ea[4]; float4 va[2];
#pragma unroll
    for (int k = 0; k < 4; ++k) ea[k] = make_float4(0.f, 0.f, 0.f, 0.f);
    va[0] = make_float4(0.f, 0.f, 0.f, 0.f);
    va[1] = make_float4(0.f, 0.f, 0.f, 0.f);

#pragma unroll
    for (int ci = 0; ci < NCHUNK; ++ci) {
        cp_wait<1>();                     // chunk ci resident
        int slot = (ci & 1) * 4;

        // my segment's m: 16 dims of rho, 8 dims of lv
        float4 dm4[4], lv4[2];
#pragma unroll
        for (int k = 0; k < 4; ++k)
            dm4[k] = sm_rho[slot + seg][warp][k * 8 + sub];
        lv4[0] = sm_lv[slot + seg][warp][sub];
        lv4[1] = sm_lv[slot + seg][warp][8 + sub];

        // refill freed slots with chunk ci+2
        if (ci + 2 < NCHUNK) {
#pragma unroll
            for (int j = 0; j < 4; ++j) {
                int m = m0 + 16 * (ci + 2) + 4 * j;
                cp_async16(smem_u32(&sm_rho[slot + j][warp][(lane & 3) * 8 + (lane >> 2)]),
                           rho_b + (size_t)m * Aq * DE);
            }
#pragma unroll
            for (int t = 0; t < 2; ++t) {
                int item = t * 32 + lane;
                int j = item >> 4, f = item & 15;
                int m = m0 + 16 * (ci + 2) + 4 * j;
                cp_async16(smem_u32(&sm_lv[slot + j][warp][(f & 1) * 8 + (f >> 1)]),
                           lv_b + (size_t)m * DH + 4 * f);
            }
        }
        cp_commit();                      // keeps group count in sync

        // 16-dim partial squared distance
        float pd = 0.f;
#pragma unroll
        for (int k = 0; k < 4; ++k) {
            float dx = cr4[k].x - dm4[k].x, dy = cr4[k].y - dm4[k].y;
            float dz = cr4[k].z - dm4[k].z, dw = cr4[k].w - dm4[k].w;
            pd = fmaf(dx, dx, pd); pd = fmaf(dy, dy, pd);
            pd = fmaf(dz, dz, pd); pd = fmaf(dw, dw, pd);
        }
        // segment reduce (8 lanes)
        pd += __shfl_xor_sync(0xffffffffu, pd, 1);
        pd += __shfl_xor_sync(0xffffffffu, pd, 2);
        pd += __shfl_xor_sync(0xffffffffu, pd, 4);

        float score = -(s_dH2[warp + 16 * ci + 4 * seg] + pd);  // LH=LE=TAU=1

        // warp-wide chunk max (values identical within a segment)
        float t1 = fmaxf(score, __shfl_xor_sync(0xffffffffu, score, 8));
        float cm = fmaxf(t1,    __shfl_xor_sync(0xffffffffu, t1, 16));

        if (cm > mx) {                    // warp-uniform; once per 4 m
            float corr = __expf(mx - cm); // exp(-inf)=0 on first chunk
            mx = cm;
            sm *= corr;
#pragma unroll
            for (int k = 0; k < 4; ++k) {
                ea[k].x *= corr; ea[k].y *= corr; ea[k].z *= corr; ea[k].w *= corr;
            }
            va[0].x *= corr; va[0].y *= corr; va[0].z *= corr; va[0].w *= corr;
            va[1].x *= corr; va[1].y *= corr; va[1].z *= corr; va[1].w *= corr;
        }
        float w = __expf(score - mx);     // one expf serves this segment's m
        sm += w;
#pragma unroll
        for (int k = 0; k < 4; ++k) {
            ea[k].x = fmaf(w, dm4[k].x, ea[k].x);
            ea[k].y = fmaf(w, dm4[k].y, ea[k].y);
            ea[k].z = fmaf(w, dm4[k].z, ea[k].z);
            ea[k].w = fmaf(w, dm4[k].w, ea[k].w);
        }
        va[0].x = fmaf(w, lv4[0].x, va[0].x);
        va[0].y = fmaf(w, lv4[0].y, va[0].y);
        va[0].z = fmaf(w, lv4[0].z, va[0].z);
        va[0].w = fmaf(w, lv4[0].w, va[0].w);
        va[1].x = fmaf(w, lv4[1].x, va[1].x);
        va[1].y = fmaf(w, lv4[1].y, va[1].y);
        va[1].z = fmaf(w, lv4[1].z, va[1].z);
        va[1].w = fmaf(w, lv4[1].w, va[1].w);
    }
    cp_wait<0>();                         // drain

    // cross-segment merge: lanes {sub, sub+8, sub+16, sub+24} hold the same
    // dims for disjoint m-subsets, all consistently scaled by the shared mx.
#pragma unroll
    for (int o = 8; o <= 16; o <<= 1) {
#pragma unroll
        for (int k = 0; k < 4; ++k) {
            ea[k].x += __shfl_xor_sync(0xffffffffu, ea[k].x, o);
            ea[k].y += __shfl_xor_sync(0xffffffffu, ea[k].y, o);
            ea[k].z += __shfl_xor_sync(0xffffffffu, ea[k].z, o);
            ea[k].w += __shfl_xor_sync(0xffffffffu, ea[k].w, o);
        }
        va[0].x += __shfl_xor_sync(0xffffffffu, va[0].x, o);
        va[0].y += __shfl_xor_sync(0xffffffffu, va[0].y, o);
        va[0].z += __shfl_xor_sync(0xffffffffu, va[0].z, o);
        va[0].w += __shfl_xor_sync(0xffffffffu, va[0].w, o);
        va[1].x += __shfl_xor_sync(0xffffffffu, va[1].x, o);
        va[1].y += __shfl_xor_sync(0xffffffffu, va[1].y, o);
        va[1].z += __shfl_xor_sync(0xffffffffu, va[1].z, o);
        va[1].w += __shfl_xor_sync(0xffffffffu, va[1].w, o);
        sm += __shfl_xor_sync(0xffffffffu, sm, o);
    }

    if (seg == 0) {                       // lanes 0-7 write the warp result
#pragma unroll
        for (int k = 0; k < 4; ++k) s_e4[warp][4 * sub + k] = ea[k];
        s_v4[warp][2 * sub + 0] = va[0];
        s_v4[warp][2 * sub + 1] = va[1];
    }
    if (lane == 0) { s_mx[warp] = mx; s_sm[warp] = sm; }
    __syncthreads();

    // ---- merge 4 warps, write block partial (unnormalized, at block max) ----
    float gmax = fmaxf(fmaxf(s_mx[0], s_mx[1]), fmaxf(s_mx[2], s_mx[3]));
    float c0 = __expf(s_mx[0] - gmax), c1 = __expf(s_mx[1] - gmax);
    float c2 = __expf(s_mx[2] - gmax), c3 = __expf(s_mx[3] - gmax);

    const float* se = (const float*)s_e4;     // [4][128]
    const float* sv = (const float*)s_v4;     // [4][64]
    g_pe[(size_t)bas * DE + tid] =
        se[0 * DE + tid] * c0 + se[1 * DE + tid] * c1 +
        se[2 * DE + tid] * c2 + se[3 * DE + tid] * c3;
    if (tid < DH)
        g_pv[(size_t)bas * DH + tid] =
            sv[0 * DH + tid] * c0 + sv[1 * DH + tid] * c1 +
            sv[2 * DH + tid] * c2 + sv[3 * DH + tid] * c3;
    if (tid == 0) {
        g_pmx[bas] = gmax;
        g_psm[bas] = s_sm[0] * c0 + s_sm[1] * c1 + s_sm[2] * c2 + s_sm[3] * c3;
    }
}

// ---------------------------------------------------------------------------
// Kernel 3: merge SPLIT partials per (b,a); exp-map, projections, LayerNorm.
// ---------------------------------------------------------------------------
__global__ __launch_bounds__(128) void k_final(
    const float* __restrict__ curr_hyp,   // [B, DH]
    const float* __restrict__ We,         // [ZE, DE]
    const float* __restrict__ Wh,         // [ZH, DH]
    const float* __restrict__ gamma,      // [ZDIM]
    const float* __restrict__ beta,       // [ZDIM]
    float* __restrict__ out)              // [B, A, ZDIM]
{
    int ba = blockIdx.x;                  // b*64 + a
    int b  = ba >> 6;
    int tid = threadIdx.x, warp = tid >> 5, lane = tid & 31;

    __shared__ float s_eout[DE], s_vv[DH], s_h[DH], s_wred[4];

    float mx0 = g_pmx[ba * SPLIT + 0], mx1 = g_pmx[ba * SPLIT + 1];
    float mx2 = g_pmx[ba * SPLIT + 2], mx3 = g_pmx[ba * SPLIT + 3];
    float G = fmaxf(fmaxf(mx0, mx1), fmaxf(mx2, mx3));
    float c0 = __expf(mx0 - G), c1 = __expf(mx1 - G);
    float c2 = __expf(mx2 - G), c3 = __expf(mx3 - G);
    float inv = __fdividef(1.0f,
        g_psm[ba * SPLIT + 0] * c0 + g_psm[ba * SPLIT + 1] * c1 +
        g_psm[ba * SPLIT + 2] * c2 + g_psm[ba * SPLIT + 3] * c3);

    s_eout[tid] = (g_pe[((size_t)ba * SPLIT + 0) * DE + tid] * c0 +
                   g_pe[((size_t)ba * SPLIT + 1) * DE + tid] * c1 +
                   g_pe[((size_t)ba * SPLIT + 2) * DE + tid] * c2 +
                   g_pe[((size_t)ba * SPLIT + 3) * DE + tid] * c3) * inv;
    if (tid < DH)
        s_vv[tid] = (g_pv[((size_t)ba * SPLIT + 0) * DH + tid] * c0 +
                     g_pv[((size_t)ba * SPLIT + 1) * DH + tid] * c1 +
                     g_pv[((size_t)ba * SPLIT + 2) * DH + tid] * c2 +
                     g_pv[((size_t)ba * SPLIT + 3) * DH + tid] * c3) * inv;
    __syncthreads();

    // ---- exp-map (warp 0; lane owns dims lane and lane+32) ----
    if (warp == 0) {
        float x0 = curr_hyp[b * DH + lane], x1 = curr_hyp[b * DH + lane + 32];
        float xn2   = wredsum(x0 * x0 + x1 * x1);
        float xnorm = fmaxf(sqrtf(xn2), 1e-15f);
        float sx    = xnorm > MAXN ? __fdividef(MAXN, xnorm) : 1.0f;
        x0 *= sx; x1 *= sx;
        float x2  = xn2 * sx * sx;
        float lam = 2.0f * __fdividef(1.0f, fmaxf(1.0f - x2, 1e-15f));

        float v0 = s_vv[lane], v1 = s_vv[lane + 32];
        float vn2    = wredsum(v0 * v0 + v1 * v1);
        float vnorm  = fmaxf(sqrtf(vn2), 1e-15f);
        float factor = tanhf(lam * vnorm * 0.5f);
        float f      = __fdividef(factor, vnorm);
        float y0 = v0 * f, y1 = v1 * f;

        float yn2   = wredsum(y0 * y0 + y1 * y1);
        float ynorm = fmaxf(sqrtf(yn2), 1e-15f);
        float sy    = ynorm > MAXN ? __fdividef(MAXN, ynorm) : 1.0f;
        y0 *= sy; y1 *= sy;
        float y2s = yn2 * sy * sy;

        float xy  = wredsum(x0 * y0 + x1 * y1);
        float cA  = 1.0f + 2.0f * xy + y2s;
        float cY  = 1.0f - x2;
        float den = 1.0f + 2.0f * xy + x2 * y2s;
        float id  = __fdividef(1.0f, fmaxf(den, 1e-15f));
        float o0  = (cA * x0 + cY * y0) * id;
        float o1  = (cA * x1 + cY * y1) * id;

        float on2   = wredsum(o0 * o0 + o1 * o1);
        float onorm = fmaxf(sqrtf(on2), 1e-15f);
        float so    = onorm > MAXN ? __fdividef(MAXN, onorm) : 1.0f;
        s_h[lane] = o0 * so; s_h[lane + 32] = o1 * so;
    }
    __syncthreads();

    // ---- projections z = [e_out @ We^T, h_out @ Wh^T] ----
    float z;
    if (tid < ZE) {
        const float4* wr = (const float4*)(We + (size_t)tid * DE);
        float acc = 0.f;
#pragma unroll
        for (int k = 0; k < DE / 4; k++) {
            float4 wv = wr[k];
            acc += wv.x * s_eout[4 * k]     + wv.y * s_eout[4 * k + 1]
                 + wv.z * s_eout[4 * k + 2] + wv.w * s_eout[4 * k + 3];
        }
        z = acc;
    } else {
        const float4* wr = (const float4*)(Wh + (size_t)(tid - ZE) * DH);
        float acc = 0.f;
#pragma unroll
        for (int k = 0; k < DH / 4; k++) {
            float4 wv = wr[k];
            acc += wv.x * s_h[4 * k]     + wv.y * s_h[4 * k + 1]
                 + wv.z * s_h[4 * k + 2] + wv.w * s_h[4 * k + 3];
        }
        z = acc;
    }

    // ---- LayerNorm over ZDIM = 128 threads ----
    float p = wredsum(z);
    if (lane == 0) s_wred[warp] = p;
    __syncthreads();
    float mean = (s_wred[0] + s_wred[1] + s_wred[2] + s_wred[3]) * (1.0f / ZDIM);
    float dz = z - mean;
    float q = wredsum(dz * dz);
    __syncthreads();
    if (lane == 0) s_wred[warp] = q;
    __syncthreads();
    float var = (s_wred[0] + s_wred[1] + s_wred[2] + s_wred[3]) * (1.0f / ZDIM);

    out[(size_t)ba * ZDIM + tid] = dz * __frsqrt_rn(var + 1e-5f) * gamma[tid] + beta[tid];
}

// ---------------------------------------------------------------------------
extern "C" void kernel_launch(void* const* d_in, const int* in_sizes, int n_in,
                              void* d_out, int out_size)
{
    const float* curr_rho = (const float*)d_in[0];   // [B,A,de]
    const float* curr_hyp = (const float*)d_in[1];   // [B,dh]
    const float* demo_rho = (const float*)d_in[2];   // [B,N,L,A,de]
    const float* demo_hyp = (const float*)d_in[3];   // [B,N,L,dh]
    const float* We       = (const float*)d_in[4];   // [z_e,de]
    const float* Wh       = (const float*)d_in[5];   // [z_h,dh]
    const float* gamma    = (const float*)d_in[6];   // [z]
    const float* beta     = (const float*)d_in[7];   // [z]
    float* out = (float*)d_out;

    k_hyp<<<(Bq * Mq) / 4, 128>>>(curr_hyp, demo_hyp);
    k_attn_part<<<Bq * Aq * SPLIT, 128>>>(curr_rho, demo_rho);
    k_final<<<Bq * Aq, 128>>>(curr_hyp, We, Wh, gamma, beta, out);
}

// round 13
// speedup vs baseline: 1.5414x; 1.5414x over previous
#include <cuda_runtime.h>
#include <math.h>
#include <stdint.h>

// Problem constants (fixed by the dataset shapes)
#define Bq    8
#define Aq    64
#define DE    128
#define DH    64
#define Mq    512            // N*L = 8*64
#define ZDIM  128
#define ZE    64
#define ZH    64
#define SPLIT 4              // m-splits per (b,a)
#define MBLK  (Mq / SPLIT)   // 128 m per block
#define MPW   (MBLK / 4)     // 32 m per warp
#define CHUNK 4              // m processed per loop step
#define NCHUNK (MPW / CHUNK) // 8
#define MAXN  0.99999f       // (1 - 1e-5)/sqrt(c), c = 1
#define ARGC  0.9999999f     // 1 - 1e-7

// Scratch (device globals: no allocation in kernel_launch)
__device__ float g_dH2[Bq * Mq];                       // 16 KB
__device__ float g_logv[Bq * Mq * DH];                 // 1 MB (L2-resident)
__device__ float g_pmx[Bq * Aq * SPLIT];               // partial max
__device__ float g_psm[Bq * Aq * SPLIT];               // partial sum-exp
__device__ float g_pe [Bq * Aq * SPLIT * DE];          // partial e-acc
__device__ float g_pv [Bq * Aq * SPLIT * DH];          // partial v-acc
__device__ int   g_cnt[Bq * Aq];                       // arrival counters (zero-init)

__device__ __forceinline__ float wredsum(float v) {
#pragma unroll
    for (int o = 16; o; o >>= 1) v += __shfl_xor_sync(0xffffffffu, v, o);
    return v;
}

__device__ __forceinline__ uint32_t smem_u32(const void* p) {
    return (uint32_t)__cvta_generic_to_shared(p);
}
__device__ __forceinline__ void cp_async16(uint32_t dst, const void* src) {
    asm volatile("cp.async.cg.shared.global [%0], [%1], 16;\n" :: "r"(dst), "l"(src));
}
__device__ __forceinline__ void cp_async8(uint32_t dst, const void* src) {
    asm volatile("cp.async.ca.shared.global [%0], [%1], 8;\n" :: "r"(dst), "l"(src));
}
__device__ __forceinline__ void cp_commit() {
    asm volatile("cp.async.commit_group;\n" ::: "memory");
}
template <int N>
__device__ __forceinline__ void cp_wait() {
    asm volatile("cp.async.wait_group %0;\n" :: "n"(N) : "memory");
}

// ---------------------------------------------------------------------------
// Kernel 1: per (b, m) hyperbolic precompute (unchanged from R8, passing).
// ---------------------------------------------------------------------------
__global__ __launch_bounds__(128) void k_hyp(
    const float* __restrict__ curr_hyp,   // [B, DH]
    const float* __restrict__ demo_hyp)   // [B, M, DH]
{
    int warp = threadIdx.x >> 5, lane = threadIdx.x & 31;
    int idx  = blockIdx.x * 4 + warp;     // [0, B*M)
    int b    = idx >> 9;                  // Mq = 512

    const float2 xv = ((const float2*)(curr_hyp + (size_t)b * DH))[lane];
    const float2 yv = ((const float2*)(demo_hyp + (size_t)idx * DH))[lane];

    float pxn = fmaf(xv.x, xv.x, xv.y * xv.y);
    float pyn = fmaf(yv.x, yv.x, yv.y * yv.y);
    float pxy = fmaf(xv.x, yv.x, xv.y * yv.y);
#pragma unroll
    for (int o = 16; o; o >>= 1) {        // 3 independent chains, interleaved
        pxn += __shfl_xor_sync(0xffffffffu, pxn, o);
        pyn += __shfl_xor_sync(0xffffffffu, pyn, o);
        pxy += __shfl_xor_sync(0xffffffffu, pxy, o);
    }

    float xnorm = fmaxf(sqrtf(pxn), 1e-15f);
    float sx    = xnorm > MAXN ? __fdividef(MAXN, xnorm) : 1.0f;
    float ynorm = fmaxf(sqrtf(pyn), 1e-15f);
    float sy    = ynorm > MAXN ? __fdividef(MAXN, ynorm) : 1.0f;

    float x2 = pxn * sx * sx, y2 = pyn * sy * sy, xy = pxy * sx * sy;

    float cA  = 1.0f - 2.0f * xy + y2;    // coeff of a = -x
    float cY  = 1.0f - x2;                // coeff of y
    float den = 1.0f - 2.0f * xy + x2 * y2;
    float id  = __fdividef(1.0f, fmaxf(den, 1e-15f));

    // |u|^2 = id^2 * (cA^2 x2 - 2 cA cY xy + cY^2 y2)
    float un2   = (cA * cA * x2 - 2.0f * cA * cY * xy + cY * cY * y2) * id * id;
    float unorm = fmaxf(sqrtf(un2), 1e-15f);
    float arg   = fminf(unorm, ARGC);
    float at    = 0.5f * __logf(__fdividef(1.0f + arg, 1.0f - arg));   // atanh

    float scale = fmaxf(cY, 1e-15f) * __fdividef(at, unorm);

    float u0 = (cA * (-(xv.x * sx)) + cY * (yv.x * sy)) * id;
    float u1 = (cA * (-(xv.y * sx)) + cY * (yv.y * sy)) * id;

    ((float2*)(g_logv + (size_t)idx * DH))[lane] = make_float2(scale * u0, scale * u1);
    if (lane == 0) { float d = 2.0f * at; g_dH2[idx] = d * d; }
}

// ---------------------------------------------------------------------------
// Kernel 2: partial online-softmax attention (EXACT R8 mainloop), with the
// finalize (merge + exp-map + projections + LayerNorm) FUSED via the
// threadfence-reduction pattern: the last-arriving of the 4 split blocks per
// (b,a) performs the merge and resets the counter (graph-replay safe).
// Output is deterministic: all partials are deterministic and merge order is
// fixed by index, independent of which block merges.
// ---------------------------------------------------------------------------
__global__ __launch_bounds__(128) void k_attn_part(
    const float* __restrict__ curr_rho,   // [B, A, DE]
    const float* __restrict__ demo_rho,   // [B, M, A, DE]
    const float* __restrict__ curr_hyp,   // [B, DH]
    const float* __restrict__ We,         // [ZE, DE]
    const float* __restrict__ Wh,         // [ZH, DH]
    const float* __restrict__ gamma,      // [ZDIM]
    const float* __restrict__ beta,       // [ZDIM]
    float* __restrict__ out)              // [B, A, ZDIM]
{
    int bas = blockIdx.x;                 // ((b*64 + a)*SPLIT + s)
    int s   = bas & (SPLIT - 1);
    int ba  = bas >> 2;
    int b   = ba >> 6, a = ba & 63;
    int tid = threadIdx.x, warp = tid >> 5, lane = tid & 31;

    __shared__ float4 sm_rho[8][4][32];   // 16 KB (8 m-slots)
    __shared__ float2 sm_lv [8][4][32];   //  8 KB
    __shared__ float  s_dH2[MBLK];        // 512 B
    __shared__ float  s_mx[4], s_sm[4], s_e[4][DE], s_v[4][DH];
    __shared__ int    s_last;

    s_dH2[tid] = g_dH2[(size_t)b * Mq + s * MBLK + tid];
    __syncthreads();

    const float4 cr = ((const float4*)(curr_rho + ((size_t)b * Aq + a) * DE))[lane];

    const float* rho_b = demo_rho + ((size_t)b * Mq * Aq + a) * DE + 4 * lane;
    const float* lv_b  = g_logv + (size_t)b * Mq * DH + 2 * lane;
    int m0 = s * MBLK + warp;             // this warp's first m; stride 4

    // prologue: fill 2 chunks (one commit group per chunk)
#pragma unroll
    for (int c = 0; c < 2; ++c) {
#pragma unroll
        for (int j = 0; j < CHUNK; ++j) {
            int m = m0 + 16 * c + 4 * j;
            cp_async16(smem_u32(&sm_rho[4 * c + j][warp][lane]),
                       rho_b + (size_t)m * Aq * DE);
            cp_async8 (smem_u32(&sm_lv [4 * c + j][warp][lane]),
                       lv_b + (size_t)m * DH);
        }
        cp_commit();
    }

    float  mx = -INFINITY, sm = 0.0f;
    float4 ea = make_float4(0.f, 0.f, 0.f, 0.f);
    float2 va = make_float2(0.f, 0.f);

#pragma unroll
    for (int ci = 0; ci < NCHUNK; ++ci) {
        cp_wait<1>();                     // chunk ci resident (for this lane)
        int slot = (ci & 1) * CHUNK;

        float4 dm[CHUNK]; float2 lv[CHUNK];
#pragma unroll
        for (int j = 0; j < CHUNK; ++j) {
            dm[j] = sm_rho[slot + j][warp][lane];
            lv[j] = sm_lv [slot + j][warp][lane];
        }

        // refill the freed slot with chunk ci+2
        if (ci + 2 < NCHUNK) {
#pragma unroll
            for (int j = 0; j < CHUNK; ++j) {
                int m = m0 + 16 * (ci + 2) + 4 * j;
                cp_async16(smem_u32(&sm_rho[slot + j][warp][lane]),
                           rho_b + (size_t)m * Aq * DE);
                cp_async8 (smem_u32(&sm_lv [slot + j][warp][lane]),
                           lv_b + (size_t)m * DH);
            }
        }
        cp_commit();                      // (possibly empty) keeps group count

        // 4 partial squared distances, interleaved butterfly
        float p[CHUNK];
#pragma unroll
        for (int j = 0; j < CHUNK; ++j) {
            float dx = cr.x - dm[j].x, dy = cr.y - dm[j].y;
            float dz = cr.z - dm[j].z, dw = cr.w - dm[j].w;
            p[j] = fmaf(dx, dx, fmaf(dy, dy, fmaf(dz, dz, dw * dw)));
        }
#pragma unroll
        for (int o = 16; o; o >>= 1) {
#pragma unroll
            for (int j = 0; j < CHUNK; ++j)
                p[j] += __shfl_xor_sync(0xffffffffu, p[j], o);
        }

        float sc[CHUNK];
#pragma unroll
        for (int j = 0; j < CHUNK; ++j)
            sc[j] = -(s_dH2[warp + 16 * ci + 4 * j] + p[j]);   // LH=LE=TAU=1

        float cm = fmaxf(fmaxf(sc[0], sc[1]), fmaxf(sc[2], sc[3]));
        if (cm > mx) {                    // warp-uniform; once per 4 m
            float corr = __expf(mx - cm); // exp(-inf)=0 on first chunk
            mx = cm;
            sm *= corr;
            ea.x *= corr; ea.y *= corr; ea.z *= corr; ea.w *= corr;
            va.x *= corr; va.y *= corr;
        }
#pragma unroll
        for (int j = 0; j < CHUNK; ++j) {
            float w = __expf(sc[j] - mx);
            sm += w;
            ea.x = fmaf(w, dm[j].x, ea.x);
            ea.y = fmaf(w, dm[j].y, ea.y);
            ea.z = fmaf(w, dm[j].z, ea.z);
            ea.w = fmaf(w, dm[j].w, ea.w);
            va.x = fmaf(w, lv[j].x, va.x);
            va.y = fmaf(w, lv[j].y, va.y);
        }
    }
    cp_wait<0>();                         // drain before smem reuse

    // ---- merge 4 warps, write block partial (unnormalized, at block max) ----
    s_e[warp][4 * lane + 0] = ea.x;  s_e[warp][4 * lane + 1] = ea.y;
    s_e[warp][4 * lane + 2] = ea.z;  s_e[warp][4 * lane + 3] = ea.w;
    s_v[warp][2 * lane + 0] = va.x;  s_v[warp][2 * lane + 1] = va.y;
    if (lane == 0) { s_mx[warp] = mx; s_sm[warp] = sm; }
    __syncthreads();

    {
        float gmax = fmaxf(fmaxf(s_mx[0], s_mx[1]), fmaxf(s_mx[2], s_mx[3]));
        float c0 = __expf(s_mx[0] - gmax), c1 = __expf(s_mx[1] - gmax);
        float c2 = __expf(s_mx[2] - gmax), c3 = __expf(s_mx[3] - gmax);

        g_pe[(size_t)bas * DE + tid] = s_e[0][tid] * c0 + s_e[1][tid] * c1 +
                                       s_e[2][tid] * c2 + s_e[3][tid] * c3;
        if (tid < DH)
            g_pv[(size_t)bas * DH + tid] = s_v[0][tid] * c0 + s_v[1][tid] * c1 +
                                           s_v[2][tid] * c2 + s_v[3][tid] * c3;
        if (tid == 0) {
            g_pmx[bas] = gmax;
            g_psm[bas] = s_sm[0] * c0 + s_sm[1] * c1 + s_sm[2] * c2 + s_sm[3] * c3;
        }
    }

    // ---- arrival protocol: last split-block for this ba does the finalize ----
    __threadfence();                      // release: partials visible before arrival
    if (tid == 0) {
        int old = atomicAdd(&g_cnt[ba], 1);
        s_last = (old == SPLIT - 1);
        if (s_last) g_cnt[ba] = 0;        // reset for the next graph replay
    }
    __syncthreads();
    if (!s_last) return;
    __threadfence();                      // acquire: see all partials

    // ================= finalize (former k_final body) =================
    float* s_eout = s_e[0];               // reuse smem (after barrier above)
    float* s_vv   = s_v[0];
    float* s_h    = s_v[1];
    float* s_wred = s_mx;

    float mx0 = __ldcg(&g_pmx[ba * SPLIT + 0]), mx1 = __ldcg(&g_pmx[ba * SPLIT + 1]);
    float mx2 = __ldcg(&g_pmx[ba * SPLIT + 2]), mx3 = __ldcg(&g_pmx[ba * SPLIT + 3]);
    float G = fmaxf(fmaxf(mx0, mx1), fmaxf(mx2, mx3));
    float c0 = __expf(mx0 - G), c1 = __expf(mx1 - G);
    float c2 = __expf(mx2 - G), c3 = __expf(mx3 - G);
    float inv = __fdividef(1.0f,
        __ldcg(&g_psm[ba * SPLIT + 0]) * c0 + __ldcg(&g_psm[ba * SPLIT + 1]) * c1 +
        __ldcg(&g_psm[ba * SPLIT + 2]) * c2 + __ldcg(&g_psm[ba * SPLIT + 3]) * c3);

    float eo = (__ldcg(&g_pe[((size_t)ba * SPLIT + 0) * DE + tid]) * c0 +
                __ldcg(&g_pe[((size_t)ba * SPLIT + 1) * DE + tid]) * c1 +
                __ldcg(&g_pe[((size_t)ba * SPLIT + 2) * DE + tid]) * c2 +
                __ldcg(&g_pe[((size_t)ba * SPLIT + 3) * DE + tid]) * c3) * inv;
    float vv = 0.0f;
    if (tid < DH)
        vv = (__ldcg(&g_pv[((size_t)ba * SPLIT + 0) * DH + tid]) * c0 +
              __ldcg(&g_pv[((size_t)ba * SPLIT + 1) * DH + tid]) * c1 +
              __ldcg(&g_pv[((size_t)ba * SPLIT + 2) * DH + tid]) * c2 +
              __ldcg(&g_pv[((size_t)ba * SPLIT + 3) * DH + tid]) * c3) * inv;
    __syncthreads();                      // s_e/s_v reads above done pre-fusion
    s_eout[tid] = eo;
    if (tid < DH) s_vv[tid] = vv;
    __syncthreads();

    // ---- exp-map (warp 0; lane owns dims lane and lane+32) ----
    if (warp == 0) {
        float x0 = curr_hyp[b * DH + lane], x1 = curr_hyp[b * DH + lane + 32];
        float xn2   = wredsum(x0 * x0 + x1 * x1);
        float xnorm = fmaxf(sqrtf(xn2), 1e-15f);
        float sx    = xnorm > MAXN ? __fdividef(MAXN, xnorm) : 1.0f;
        x0 *= sx; x1 *= sx;
        float x2  = xn2 * sx * sx;
        float lam = 2.0f * __fdividef(1.0f, fmaxf(1.0f - x2, 1e-15f));

        float v0 = s_vv[lane], v1 = s_vv[lane + 32];
        float vn2    = wredsum(v0 * v0 + v1 * v1);
        float vnorm  = fmaxf(sqrtf(vn2), 1e-15f);
        float factor = tanhf(lam * vnorm * 0.5f);
        float f      = __fdividef(factor, vnorm);
        float y0 = v0 * f, y1 = v1 * f;

        float yn2   = wredsum(y0 * y0 + y1 * y1);
        float ynorm = fmaxf(sqrtf(yn2), 1e-15f);
        float sy    = ynorm > MAXN ? __fdividef(MAXN, ynorm) : 1.0f;
        y0 *= sy; y1 *= sy;
        float y2s = yn2 * sy * sy;

        float xy  = wredsum(x0 * y0 + x1 * y1);
        float cAe = 1.0f + 2.0f * xy + y2s;
        float cYe = 1.0f - x2;
        float den = 1.0f + 2.0f * xy + x2 * y2s;
        float id  = __fdividef(1.0f, fmaxf(den, 1e-15f));
        float o0  = (cAe * x0 + cYe * y0) * id;
        float o1  = (cAe * x1 + cYe * y1) * id;

        float on2   = wredsum(o0 * o0 + o1 * o1);
        float onorm = fmaxf(sqrtf(on2), 1e-15f);
        float so    = onorm > MAXN ? __fdividef(MAXN, onorm) : 1.0f;
        s_h[lane] = o0 * so; s_h[lane + 32] = o1 * so;
    }
    __syncthreads();

    // ---- projections z = [e_out @ We^T, h_out @ Wh^T] ----
    float z;
    if (tid < ZE) {
        const float4* wr = (const float4*)(We + (size_t)tid * DE);
        float acc = 0.f;
#pragma unroll
        for (int k = 0; k < DE / 4; k++) {
            float4 wv = wr[k];
            acc += wv.x * s_eout[4 * k]     + wv.y * s_eout[4 * k + 1]
                 + wv.z * s_eout[4 * k + 2] + wv.w * s_eout[4 * k + 3];
        }
        z = acc;
    } else {
        const float4* wr = (const float4*)(Wh + (size_t)(tid - ZE) * DH);
        float acc = 0.f;
#pragma unroll
        for (int k = 0; k < DH / 4; k++) {
            float4 wv = wr[k];
            acc += wv.x * s_h[4 * k]     + wv.y * s_h[4 * k + 1]
                 + wv.z * s_h[4 * k + 2] + wv.w * s_h[4 * k + 3];
        }
        z = acc;
    }

    // ---- LayerNorm over ZDIM = 128 threads ----
    float p = wredsum(z);
    if (lane == 0) s_wred[warp] = p;
    __syncthreads();
    float mean = (s_wred[0] + s_wred[1] + s_wred[2] + s_wred[3]) * (1.0f / ZDIM);
    float dz = z - mean;
    float q = wredsum(dz * dz);
    __syncthreads();
    if (lane == 0) s_wred[warp] = q;
    __syncthreads();
    float var = (s_wred[0] + s_wred[1] + s_wred[2] + s_wred[3]) * (1.0f / ZDIM);

    out[(size_t)ba * ZDIM + tid] = dz * __frsqrt_rn(var + 1e-5f) * gamma[tid] + beta[tid];
}

// ---------------------------------------------------------------------------
extern "C" void kernel_launch(void* const* d_in, const int* in_sizes, int n_in,
                              void* d_out, int out_size)
{
    const float* curr_rho = (const float*)d_in[0];   // [B,A,de]
    const float* curr_hyp = (const float*)d_in[1];   // [B,dh]
    const float* demo_rho = (const float*)d_in[2];   // [B,N,L,A,de]
    const float* demo_hyp = (const float*)d_in[3];   // [B,N,L,dh]
    const float* We       = (const float*)d_in[4];   // [z_e,de]
    const float* Wh       = (const float*)d_in[5];   // [z_h,dh]
    const float* gamma    = (const float*)d_in[6];   // [z]
    const float* beta     = (const float*)d_in[7];   // [z]
    float* out = (float*)d_out;

    k_hyp<<<(Bq * Mq) / 4, 128>>>(curr_hyp, demo_hyp);
    k_attn_part<<<Bq * Aq * SPLIT, 128>>>(curr_rho, demo_rho, curr_hyp,
                                          We, Wh, gamma, beta, out);
}